// round 12
// baseline (speedup 1.0000x reference)
#include <cuda_runtime.h>
#include <cstdint>
#include <cstddef>

// Problem constants (fixed by setup_inputs: d=256, L=8, per=8192, deg=8)
#define D        256
#define PER      8192
#define NNODES   65536
#define DEG      8
#define EPL      65536
#define NLVL     7
#define NCTA     148
#define NTHR     512                 // compute threads (16 warps)
#define CWARPS   4                   // dedicated copy warps per CTA
#define NTHR_TOT (NTHR + CWARPS * 32)   // 640

// named barrier for the 512 compute threads only (copy warps never join)
#define CBAR() asm volatile("bar.sync 1, %0;" :: "n"(NTHR) : "memory")

// ---------------- device scratch (no allocation allowed) ----------------
__device__ float  g_H[PER * D];          // H for current level (lives in L2)
__device__ float  g_X2[PER * D];         // aggregate output (lives in L2)
__device__ float  g_y[PER * D];          // y = x + x2 for last-layer rows
__device__ float  g_asrc2[2][PER];       // ping-pong a_src
__device__ float  g_adst[PER];
__device__ double g_psum[NCTA];          // per-CTA LN partials (no atomics)
__device__ double g_psq[NCTA];
__device__ int    g_count = 0;           // grid barrier state
__device__ int    g_sense = 0;

__device__ __forceinline__ void cp16(uint32_t dst, const float* src) {
    asm volatile("cp.async.cg.shared.global [%0], [%1], 16;\n" :: "r"(dst), "l"(src));
}

__device__ __forceinline__ void mma_tf32(float* c, const uint32_t* a, const uint32_t* b) {
    asm volatile(
        "mma.sync.aligned.m16n8k8.row.col.f32.tf32.tf32.f32 "
        "{%0,%1,%2,%3}, {%4,%5,%6,%7}, {%8,%9}, {%0,%1,%2,%3};\n"
        : "+f"(c[0]), "+f"(c[1]), "+f"(c[2]), "+f"(c[3])
        : "r"(a[0]), "r"(a[1]), "r"(a[2]), "r"(a[3]), "r"(b[0]), "r"(b[1]));
}

// grid-wide barrier over compute warps of all CTAs
__device__ __forceinline__ void gbar(int& ls) {
    CBAR();
    if (threadIdx.x == 0) {
        __threadfence();
        if (atomicAdd(&g_count, 1) == NCTA - 1) {
            g_count = 0;
            __threadfence();
            atomicExch(&g_sense, ls);
        } else {
            while (*(volatile int*)&g_sense != ls) __nanosleep(64);
            __threadfence();
        }
    }
    CBAR();
    ls ^= 1;
}

// ---------------- GEMM phase: Hout[8192 x 256] = A @ W^T  (tf32 mma) ----------
// Tiles 64x64, 512 tiles strided over CTAs. 16 warps, warp tile 16x16.
__device__ __forceinline__ void gemm_phase(const float* __restrict__ A,
                                           const float* __restrict__ W,
                                           float* __restrict__ Hout,
                                           float (*As)[64][32], float (*Bs)[64][32],
                                           int cta, int tid)
{
    const int warp = tid >> 5, lane = tid & 31;
    const int wm = (warp & 3) * 16, wn = (warp >> 2) * 16;
    const int r = tid >> 3, sg = tid & 7;            // staging: 1 A seg + 1 B seg / thread
    const uint32_t as_base = (uint32_t)__cvta_generic_to_shared(&As[0][0][0]);
    const uint32_t bs_base = (uint32_t)__cvta_generic_to_shared(&Bs[0][0][0]);
    const uint32_t sw = (uint32_t)(((r * 32) + ((sg ^ (r & 7)) << 2)) * 4);
    const uint32_t bufstride = 64 * 32 * 4;

    for (int t = cta; t < 512; t += NCTA) {
        const int m0 = (t >> 2) * 64;
        const int n0 = (t & 3) * 64;
        float acc[2][4];
#pragma unroll
        for (int i = 0; i < 2; i++)
#pragma unroll
            for (int j = 0; j < 4; j++) acc[i][j] = 0.f;

        CBAR();   // protect smem from previous tile's readers
        cp16(as_base + sw, A + (size_t)(m0 + r) * D + sg * 4);
        cp16(bs_base + sw, W + (size_t)(n0 + r) * D + sg * 4);
        asm volatile("cp.async.commit_group;\n" ::: "memory");

#pragma unroll
        for (int c = 0; c < 8; c++) {
            if (c + 1 < 8) {
                uint32_t boff = ((c + 1) & 1) * bufstride;
                cp16(as_base + boff + sw, A + (size_t)(m0 + r) * D + (c + 1) * 32 + sg * 4);
                cp16(bs_base + boff + sw, W + (size_t)(n0 + r) * D + (c + 1) * 32 + sg * 4);
                asm volatile("cp.async.commit_group;\n" ::: "memory");
                asm volatile("cp.async.wait_group 1;\n" ::: "memory");
            } else {
                asm volatile("cp.async.wait_group 0;\n" ::: "memory");
            }
            CBAR();
            const int buf = c & 1;
#pragma unroll
            for (int kk = 0; kk < 4; kk++) {
                uint32_t a[4], b[4];
                int arow = wm + (lane & 7) + ((lane & 8) ? 8 : 0);
                int asg  = (kk * 2 + ((lane >> 4) & 1)) ^ (arow & 7);
                uint32_t aaddr = as_base + (uint32_t)(((buf * 64 + arow) * 32 + asg * 4) * 4);
                asm volatile("ldmatrix.sync.aligned.m8n8.x4.shared.b16 {%0,%1,%2,%3}, [%4];\n"
                             : "=r"(a[0]), "=r"(a[1]), "=r"(a[2]), "=r"(a[3]) : "r"(aaddr));
                int brow = wn + (lane & 7) + ((lane & 16) ? 8 : 0);
                int bsg  = (kk * 2 + ((lane >> 3) & 1)) ^ (brow & 7);
                uint32_t baddr = bs_base + (uint32_t)(((buf * 64 + brow) * 32 + bsg * 4) * 4);
                asm volatile("ldmatrix.sync.aligned.m8n8.x4.shared.b16 {%0,%1,%2,%3}, [%4];\n"
                             : "=r"(b[0]), "=r"(b[1]), "=r"(b[2]), "=r"(b[3]) : "r"(baddr));
                mma_tf32(acc[0], a, b);
                mma_tf32(acc[1], a, b + 2);
            }
            CBAR();
        }
        int row0 = m0 + wm + (lane >> 2);
#pragma unroll
        for (int nf = 0; nf < 2; nf++) {
            int col = n0 + wn + nf * 8 + (lane & 3) * 2;
            *reinterpret_cast<float2*>(&Hout[(size_t)row0 * D + col]) =
                make_float2(acc[nf][0], acc[nf][1]);
            *reinterpret_cast<float2*>(&Hout[(size_t)(row0 + 8) * D + col]) =
                make_float2(acc[nf][2], acc[nf][3]);
        }
    }
}

// ---------------- aggregate phase: warp per dst row -------------------------
__device__ __forceinline__ void agg_phase(const int* __restrict__ ei,
                                          const float* __restrict__ bias,
                                          const float* __restrict__ x,
                                          int l, const float* s_vsrc,
                                          float* red, int cta, int tid)
{
    const int warp = tid >> 5, lane = tid & 31;
    const float* asrc = g_asrc2[l & 1];
    float* anext = g_asrc2[(l + 1) & 1];
    const float4* H4 = (const float4*)g_H;
    const float4* b4 = (const float4*)bias;
    float ts = 0.f, tq = 0.f;

    for (int row = cta * 16 + warp; row < PER; row += NCTA * 16) {
        const int eb = (l - 1) * EPL + row * DEG;
        int sj[DEG]; float p[DEG];
        float ad = (l == 1) ? g_adst[row] : 0.f;
        float m = -1e30f;
#pragma unroll
        for (int j = 0; j < DEG; j++) {
            int s = ei[eb + j] - (l - 1) * PER;
            sj[j] = s;
            float a = asrc[s] + ad;
            a = a > 0.f ? a : 0.2f * a;           // leaky_relu 0.2
            p[j] = a;
            m = fmaxf(m, a);
        }
        float den = 0.f;
#pragma unroll
        for (int j = 0; j < DEG; j++) { p[j] = __expf(p[j] - m); den += p[j]; }
        float inv = 1.f / den;
#pragma unroll
        for (int j = 0; j < DEG; j++) p[j] *= inv;

        float4 a0 = b4[lane], a1 = b4[32 + lane];
#pragma unroll
        for (int j = 0; j < DEG; j++) {
            float4 h0 = H4[(size_t)sj[j] * 64 + lane];
            float4 h1 = H4[(size_t)sj[j] * 64 + 32 + lane];
            a0.x = fmaf(p[j], h0.x, a0.x); a0.y = fmaf(p[j], h0.y, a0.y);
            a0.z = fmaf(p[j], h0.z, a0.z); a0.w = fmaf(p[j], h0.w, a0.w);
            a1.x = fmaf(p[j], h1.x, a1.x); a1.y = fmaf(p[j], h1.y, a1.y);
            a1.z = fmaf(p[j], h1.z, a1.z); a1.w = fmaf(p[j], h1.w, a1.w);
        }
        if (l < NLVL) {
            ((float4*)g_X2)[(size_t)row * 64 + lane]      = a0;
            ((float4*)g_X2)[(size_t)row * 64 + 32 + lane] = a1;
            const float4* v4 = (const float4*)s_vsrc;
            float4 v0 = v4[lane], v1 = v4[32 + lane];
            float d = a0.x * v0.x + a0.y * v0.y + a0.z * v0.z + a0.w * v0.w
                    + a1.x * v1.x + a1.y * v1.y + a1.z * v1.z + a1.w * v1.w;
#pragma unroll
            for (int o = 16; o > 0; o >>= 1) d += __shfl_xor_sync(0xffffffffu, d, o);
            if (lane == 0) anext[row] = d;
        } else {
            float4 x0 = ((const float4*)x)[(size_t)(7 * PER + row) * 64 + lane];
            float4 x1 = ((const float4*)x)[(size_t)(7 * PER + row) * 64 + 32 + lane];
            a0.x += x0.x; a0.y += x0.y; a0.z += x0.z; a0.w += x0.w;
            a1.x += x1.x; a1.y += x1.y; a1.z += x1.z; a1.w += x1.w;
            ((float4*)g_y)[(size_t)row * 64 + lane]      = a0;
            ((float4*)g_y)[(size_t)row * 64 + 32 + lane] = a1;
            ts += a0.x + a0.y + a0.z + a0.w + a1.x + a1.y + a1.z + a1.w;
            tq += a0.x * a0.x + a0.y * a0.y + a0.z * a0.z + a0.w * a0.w
                + a1.x * a1.x + a1.y * a1.y + a1.z * a1.z + a1.w * a1.w;
        }
    }
    if (l == NLVL) {
#pragma unroll
        for (int o = 16; o > 0; o >>= 1) {
            ts += __shfl_xor_sync(0xffffffffu, ts, o);
            tq += __shfl_xor_sync(0xffffffffu, tq, o);
        }
        if (lane == 0) { red[warp] = ts; red[16 + warp] = tq; }
        CBAR();
        if (tid == 0) {
            float a = 0.f, b = 0.f;
#pragma unroll
            for (int j = 0; j < 16; j++) { a += red[j]; b += red[16 + j]; }
            g_psum[cta] += (double)a;
            g_psq[cta]  += (double)b;
        }
        CBAR();
    }
}

// ---------------- the persistent kernel --------------------------------------
__global__ void __launch_bounds__(NTHR_TOT, 1) persist_kernel(
    const float* __restrict__ x, const int* __restrict__ ei,
    const float* __restrict__ W, const float* __restrict__ att_src,
    const float* __restrict__ att_dst, const float* __restrict__ bias,
    const float* __restrict__ gamma, const float* __restrict__ beta,
    float* __restrict__ out,
    const float4* __restrict__ esrc, float4* __restrict__ edst, long long ec4)
{
    __shared__ float As[2][64][32];
    __shared__ float Bs[2][64][32];
    __shared__ float s_vsrc[D];
    __shared__ float s_vdst[D];
    __shared__ float red[32];
    __shared__ float sbc[2];

    const int cta = blockIdx.x;
    const int tid = threadIdx.x;

    // ===== copy warps: stream edge_attr -> out tail, no barriers, then exit ====
    // Rolling software pipeline: issue the NEXT batch's 8 loads before draining
    // the current batch's stores, so ~8 LDG.128 stay in flight continuously
    // (no load-drain bubble between batches). Evict-streaming hints keep the
    // stream from churning the chain's L2 working set.
    if (tid >= NTHR) {
        if (esrc != nullptr) {
            const int cw   = (tid - NTHR) >> 5;
            const int lane = tid & 31;
            const long long stride = (long long)NCTA * CWARPS * 32;
            long long i = ((long long)cta * CWARPS + cw) * 32 + lane;
            float4 v[8], w[8];
            if (i + 7 * stride < ec4) {
#pragma unroll
                for (int u = 0; u < 8; u++) v[u] = __ldcs(&esrc[i + u * stride]);
                // steady state: prefetch batch k+1, then drain batch k
                for (; i + 15 * stride < ec4; i += 8 * stride) {
#pragma unroll
                    for (int u = 0; u < 8; u++) w[u] = __ldcs(&esrc[i + (u + 8) * stride]);
#pragma unroll
                    for (int u = 0; u < 8; u++) __stcs(&edst[i + u * stride], v[u]);
#pragma unroll
                    for (int u = 0; u < 8; u++) v[u] = w[u];
                }
                // drain final full batch
#pragma unroll
                for (int u = 0; u < 8; u++) __stcs(&edst[i + u * stride], v[u]);
                i += 8 * stride;
            }
            for (; i < ec4; i += stride) __stcs(&edst[i], __ldcs(&esrc[i]));
        }
        return;
    }

    // ===== compute warps =======================================================
    const int warp = tid >> 5, lane = tid & 31;
    int ls = 1 ^ *((volatile int*)&g_sense);

    // P0: v-vectors (per-CTA smem), rowdots, stats over x head
    if (tid < D) {
        float s = 0.f, t = 0.f;
        for (int k = 0; k < D; k++) {
            float w2 = W[k * D + tid];
            s = fmaf(w2, att_src[k], s);
            t = fmaf(w2, att_dst[k], t);
        }
        s_vsrc[tid] = s;
        s_vdst[tid] = t;
    }
    CBAR();

    for (int idx = cta * 16 + warp; idx < 2 * PER; idx += NCTA * 16) {
        const float* A; const float* v; int r;
        if (idx < PER) { r = idx;       A = x;                    v = s_vsrc; }
        else           { r = idx - PER; A = x + (size_t)PER * D;  v = s_vdst; }
        const float4* a4 = (const float4*)(A + (size_t)r * D);
        const float4* v4 = (const float4*)v;
        float s = 0.f;
#pragma unroll
        for (int i = 0; i < 2; i++) {
            float4 a  = a4[i * 32 + lane];
            float4 vv = v4[i * 32 + lane];
            s += a.x * vv.x + a.y * vv.y + a.z * vv.z + a.w * vv.w;
        }
#pragma unroll
        for (int o = 16; o > 0; o >>= 1) s += __shfl_xor_sync(0xffffffffu, s, o);
        if (lane == 0) { if (idx < PER) g_asrc2[1][r] = s; else g_adst[r] = s; }
    }

    {
        float s = 0.f, q = 0.f;
        const float4* x4 = (const float4*)x;
        const int total4 = (NNODES - PER) * (D / 4);
        for (int i = cta * NTHR + tid; i < total4; i += NCTA * NTHR) {
            float4 v = x4[i];
            s += v.x + v.y + v.z + v.w;
            q += v.x * v.x + v.y * v.y + v.z * v.z + v.w * v.w;
        }
#pragma unroll
        for (int o = 16; o > 0; o >>= 1) {
            s += __shfl_xor_sync(0xffffffffu, s, o);
            q += __shfl_xor_sync(0xffffffffu, q, o);
        }
        if (lane == 0) { red[warp] = s; red[16 + warp] = q; }
        CBAR();
        if (tid == 0) {
            float a = 0.f, b = 0.f;
#pragma unroll
            for (int j = 0; j < 16; j++) { a += red[j]; b += red[16 + j]; }
            g_psum[cta] = (double)a;     // overwrite: no zero-init needed
            g_psq[cta]  = (double)b;
        }
    }
    gbar(ls);

    // P1: H1 = x[layer0] @ W^T
    gemm_phase(x, W, g_H, As, Bs, cta, tid);
    gbar(ls);

    // chain
    for (int l = 1; l <= NLVL; l++) {
        agg_phase(ei, bias, x, l, s_vsrc, red, cta, tid);
        gbar(ls);
        if (l < NLVL) {
            gemm_phase(g_X2, W, g_H, As, Bs, cta, tid);
            gbar(ls);
        }
    }

    // norm
    if (warp == 0) {
        double ds = 0.0, dq = 0.0;
        for (int i = lane; i < NCTA; i += 32) { ds += g_psum[i]; dq += g_psq[i]; }
#pragma unroll
        for (int o = 16; o > 0; o >>= 1) {
            ds += __shfl_xor_sync(0xffffffffu, ds, o);
            dq += __shfl_xor_sync(0xffffffffu, dq, o);
        }
        if (lane == 0) {
            double cnt  = (double)NNODES * D;
            double mean = ds / cnt;
            double var  = dq / cnt - mean * mean;
            sbc[0] = (float)mean;
            sbc[1] = rsqrtf((float)var + 1e-5f);
        }
    }
    CBAR();
    const float mu = sbc[0], rstd = sbc[1];
    const int total4 = NNODES * (D / 4);
    const int tail4  = (NNODES - PER) * (D / 4);
    for (int i = cta * NTHR + tid; i < total4; i += NCTA * NTHR) {
        float4 v = (i < tail4) ? ((const float4*)x)[i] : ((const float4*)g_y)[i - tail4];
        int c4 = i & 63;
        float4 g = ((const float4*)gamma)[c4];
        float4 b = ((const float4*)beta)[c4];
        float4 o;
        o.x = (v.x - mu) * rstd * g.x + b.x;
        o.y = (v.y - mu) * rstd * g.y + b.y;
        o.z = (v.z - mu) * rstd * g.z + b.z;
        o.w = (v.w - mu) * rstd * g.w + b.w;
        ((float4*)out)[i] = o;
    }
}

// ---------------- launch ----------------
extern "C" void kernel_launch(void* const* d_in, const int* in_sizes, int n_in,
                              void* d_out, int out_size) {
    const float* x       = (const float*)d_in[0];
    const int*   ei      = (const int*)d_in[1];
    const float* eattr   = (const float*)d_in[2];
    const float* W       = (const float*)d_in[5];
    const float* att_src = (const float*)d_in[6];
    const float* att_dst = (const float*)d_in[7];
    const float* bias    = (const float*)d_in[8];
    const float* gamma   = (const float*)d_in[9];
    const float* beta    = (const float*)d_in[10];
    float* out = (float*)d_out;

    size_t eelems = (size_t)in_sizes[2];
    bool do_copy = ((size_t)out_size >= (size_t)NNODES * D + eelems);
    const float4* e4src = do_copy ? (const float4*)eattr : nullptr;
    float4* e4dst = do_copy ? (float4*)(out + (size_t)NNODES * D) : nullptr;
    long long ec4 = do_copy ? (long long)(eelems / 4) : 0;

    persist_kernel<<<NCTA, NTHR_TOT>>>(x, ei, W, att_src, att_dst, bias, gamma, beta,
                                       out, e4src, e4dst, ec4);
}

// round 13
// speedup vs baseline: 1.0564x; 1.0564x over previous
#include <cuda_runtime.h>
#include <cstdint>
#include <cstddef>

// Problem constants (fixed by setup_inputs: d=256, L=8, per=8192, deg=8)
#define D        256
#define PER      8192
#define NNODES   65536
#define DEG      8
#define EPL      65536
#define NLVL     7
#define NCTA     148                // total CTAs (one per SM)
#define NCOMP    128                // compute CTAs (512 tiles / 128 = exactly 4)
#define NTHR     512                // compute threads per compute CTA (16 warps)
#define CWARPS   4                  // copy warps inside each compute CTA
#define NTHR_TOT (NTHR + CWARPS * 32)   // 640
#define WARPS_TOT (NTHR_TOT / 32)   // 20 warps (pure-copy CTAs use all 20)
#define TOTAL_CW (NCOMP * CWARPS + (NCTA - NCOMP) * WARPS_TOT)   // 912 copy warps

// named barrier for the 512 compute threads only (copy warps never join)
#define CBAR() asm volatile("bar.sync 1, %0;" :: "n"(NTHR) : "memory")

// ---------------- device scratch (no allocation allowed) ----------------
__device__ float  g_H[PER * D];          // H for current level (lives in L2)
__device__ float  g_X2[PER * D];         // aggregate output (lives in L2)
__device__ float  g_y[PER * D];          // y = x + x2 for last-layer rows
__device__ float  g_asrc2[2][PER];       // ping-pong a_src
__device__ float  g_adst[PER];
__device__ double g_psum[NCOMP];         // per-CTA LN partials (no atomics)
__device__ double g_psq[NCOMP];
__device__ int    g_count = 0;           // grid barrier state
__device__ int    g_sense = 0;

__device__ __forceinline__ void cp16(uint32_t dst, const float* src) {
    asm volatile("cp.async.cg.shared.global [%0], [%1], 16;\n" :: "r"(dst), "l"(src));
}

__device__ __forceinline__ void mma_tf32(float* c, const uint32_t* a, const uint32_t* b) {
    asm volatile(
        "mma.sync.aligned.m16n8k8.row.col.f32.tf32.tf32.f32 "
        "{%0,%1,%2,%3}, {%4,%5,%6,%7}, {%8,%9}, {%0,%1,%2,%3};\n"
        : "+f"(c[0]), "+f"(c[1]), "+f"(c[2]), "+f"(c[3])
        : "r"(a[0]), "r"(a[1]), "r"(a[2]), "r"(a[3]), "r"(b[0]), "r"(b[1]));
}

// grid-wide barrier over the compute warps of the NCOMP compute CTAs
__device__ __forceinline__ void gbar(int& ls) {
    CBAR();
    if (threadIdx.x == 0) {
        __threadfence();
        if (atomicAdd(&g_count, 1) == NCOMP - 1) {
            g_count = 0;
            __threadfence();
            atomicExch(&g_sense, ls);
        } else {
            while (*(volatile int*)&g_sense != ls) __nanosleep(64);
            __threadfence();
        }
    }
    CBAR();
    ls ^= 1;
}

// ---------------- copy worker: batch-8 register pipeline (R8 winner) ---------
__device__ __forceinline__ void copy_work(const float4* __restrict__ esrc,
                                          float4* __restrict__ edst,
                                          long long ec4, long long gw)
{
    const int lane = threadIdx.x & 31;
    const long long stride = (long long)TOTAL_CW * 32;
    long long i = gw * 32 + lane;
    float4 v[8];
    for (; i + 7 * stride < ec4; i += 8 * stride) {
#pragma unroll
        for (int u = 0; u < 8; u++) v[u] = __ldcs(&esrc[i + u * stride]);
#pragma unroll
        for (int u = 0; u < 8; u++) __stcs(&edst[i + u * stride], v[u]);
    }
    for (; i < ec4; i += stride) __stcs(&edst[i], __ldcs(&esrc[i]));
}

// ---------------- GEMM phase: Hout[8192 x 256] = A @ W^T  (tf32 mma) ----------
// Tiles 64x64, 512 tiles: exactly 4 per compute CTA. 16 warps, warp tile 16x16.
__device__ __forceinline__ void gemm_phase(const float* __restrict__ A,
                                           const float* __restrict__ W,
                                           float* __restrict__ Hout,
                                           float (*As)[64][32], float (*Bs)[64][32],
                                           int cta, int tid)
{
    const int warp = tid >> 5, lane = tid & 31;
    const int wm = (warp & 3) * 16, wn = (warp >> 2) * 16;
    const int r = tid >> 3, sg = tid & 7;            // staging: 1 A seg + 1 B seg / thread
    const uint32_t as_base = (uint32_t)__cvta_generic_to_shared(&As[0][0][0]);
    const uint32_t bs_base = (uint32_t)__cvta_generic_to_shared(&Bs[0][0][0]);
    const uint32_t sw = (uint32_t)(((r * 32) + ((sg ^ (r & 7)) << 2)) * 4);
    const uint32_t bufstride = 64 * 32 * 4;

    for (int t = cta; t < 512; t += NCOMP) {
        const int m0 = (t >> 2) * 64;
        const int n0 = (t & 3) * 64;
        float acc[2][4];
#pragma unroll
        for (int i = 0; i < 2; i++)
#pragma unroll
            for (int j = 0; j < 4; j++) acc[i][j] = 0.f;

        CBAR();   // protect smem from previous tile's readers
        cp16(as_base + sw, A + (size_t)(m0 + r) * D + sg * 4);
        cp16(bs_base + sw, W + (size_t)(n0 + r) * D + sg * 4);
        asm volatile("cp.async.commit_group;\n" ::: "memory");

#pragma unroll
        for (int c = 0; c < 8; c++) {
            if (c + 1 < 8) {
                uint32_t boff = ((c + 1) & 1) * bufstride;
                cp16(as_base + boff + sw, A + (size_t)(m0 + r) * D + (c + 1) * 32 + sg * 4);
                cp16(bs_base + boff + sw, W + (size_t)(n0 + r) * D + (c + 1) * 32 + sg * 4);
                asm volatile("cp.async.commit_group;\n" ::: "memory");
                asm volatile("cp.async.wait_group 1;\n" ::: "memory");
            } else {
                asm volatile("cp.async.wait_group 0;\n" ::: "memory");
            }
            CBAR();
            const int buf = c & 1;
#pragma unroll
            for (int kk = 0; kk < 4; kk++) {
                uint32_t a[4], b[4];
                int arow = wm + (lane & 7) + ((lane & 8) ? 8 : 0);
                int asg  = (kk * 2 + ((lane >> 4) & 1)) ^ (arow & 7);
                uint32_t aaddr = as_base + (uint32_t)(((buf * 64 + arow) * 32 + asg * 4) * 4);
                asm volatile("ldmatrix.sync.aligned.m8n8.x4.shared.b16 {%0,%1,%2,%3}, [%4];\n"
                             : "=r"(a[0]), "=r"(a[1]), "=r"(a[2]), "=r"(a[3]) : "r"(aaddr));
                int brow = wn + (lane & 7) + ((lane & 16) ? 8 : 0);
                int bsg  = (kk * 2 + ((lane >> 3) & 1)) ^ (brow & 7);
                uint32_t baddr = bs_base + (uint32_t)(((buf * 64 + brow) * 32 + bsg * 4) * 4);
                asm volatile("ldmatrix.sync.aligned.m8n8.x4.shared.b16 {%0,%1,%2,%3}, [%4];\n"
                             : "=r"(b[0]), "=r"(b[1]), "=r"(b[2]), "=r"(b[3]) : "r"(baddr));
                mma_tf32(acc[0], a, b);
                mma_tf32(acc[1], a, b + 2);
            }
            CBAR();
        }
        int row0 = m0 + wm + (lane >> 2);
#pragma unroll
        for (int nf = 0; nf < 2; nf++) {
            int col = n0 + wn + nf * 8 + (lane & 3) * 2;
            *reinterpret_cast<float2*>(&Hout[(size_t)row0 * D + col]) =
                make_float2(acc[nf][0], acc[nf][1]);
            *reinterpret_cast<float2*>(&Hout[(size_t)(row0 + 8) * D + col]) =
                make_float2(acc[nf][2], acc[nf][3]);
        }
    }
}

// ---------------- aggregate phase: warp per dst row -------------------------
__device__ __forceinline__ void agg_phase(const int* __restrict__ ei,
                                          const float* __restrict__ bias,
                                          const float* __restrict__ x,
                                          int l, const float* s_vsrc,
                                          float* red, int cta, int tid)
{
    const int warp = tid >> 5, lane = tid & 31;
    const float* asrc = g_asrc2[l & 1];
    float* anext = g_asrc2[(l + 1) & 1];
    const float4* H4 = (const float4*)g_H;
    const float4* b4 = (const float4*)bias;
    float ts = 0.f, tq = 0.f;

    for (int row = cta * 16 + warp; row < PER; row += NCOMP * 16) {
        const int eb = (l - 1) * EPL + row * DEG;
        int sj[DEG]; float p[DEG];
        float ad = (l == 1) ? g_adst[row] : 0.f;
        float m = -1e30f;
#pragma unroll
        for (int j = 0; j < DEG; j++) {
            int s = ei[eb + j] - (l - 1) * PER;
            sj[j] = s;
            float a = asrc[s] + ad;
            a = a > 0.f ? a : 0.2f * a;           // leaky_relu 0.2
            p[j] = a;
            m = fmaxf(m, a);
        }
        float den = 0.f;
#pragma unroll
        for (int j = 0; j < DEG; j++) { p[j] = __expf(p[j] - m); den += p[j]; }
        float inv = 1.f / den;
#pragma unroll
        for (int j = 0; j < DEG; j++) p[j] *= inv;

        float4 a0 = b4[lane], a1 = b4[32 + lane];
#pragma unroll
        for (int j = 0; j < DEG; j++) {
            float4 h0 = H4[(size_t)sj[j] * 64 + lane];
            float4 h1 = H4[(size_t)sj[j] * 64 + 32 + lane];
            a0.x = fmaf(p[j], h0.x, a0.x); a0.y = fmaf(p[j], h0.y, a0.y);
            a0.z = fmaf(p[j], h0.z, a0.z); a0.w = fmaf(p[j], h0.w, a0.w);
            a1.x = fmaf(p[j], h1.x, a1.x); a1.y = fmaf(p[j], h1.y, a1.y);
            a1.z = fmaf(p[j], h1.z, a1.z); a1.w = fmaf(p[j], h1.w, a1.w);
        }
        if (l < NLVL) {
            ((float4*)g_X2)[(size_t)row * 64 + lane]      = a0;
            ((float4*)g_X2)[(size_t)row * 64 + 32 + lane] = a1;
            const float4* v4 = (const float4*)s_vsrc;
            float4 v0 = v4[lane], v1 = v4[32 + lane];
            float d = a0.x * v0.x + a0.y * v0.y + a0.z * v0.z + a0.w * v0.w
                    + a1.x * v1.x + a1.y * v1.y + a1.z * v1.z + a1.w * v1.w;
#pragma unroll
            for (int o = 16; o > 0; o >>= 1) d += __shfl_xor_sync(0xffffffffu, d, o);
            if (lane == 0) anext[row] = d;
        } else {
            float4 x0 = ((const float4*)x)[(size_t)(7 * PER + row) * 64 + lane];
            float4 x1 = ((const float4*)x)[(size_t)(7 * PER + row) * 64 + 32 + lane];
            a0.x += x0.x; a0.y += x0.y; a0.z += x0.z; a0.w += x0.w;
            a1.x += x1.x; a1.y += x1.y; a1.z += x1.z; a1.w += x1.w;
            ((float4*)g_y)[(size_t)row * 64 + lane]      = a0;
            ((float4*)g_y)[(size_t)row * 64 + 32 + lane] = a1;
            ts += a0.x + a0.y + a0.z + a0.w + a1.x + a1.y + a1.z + a1.w;
            tq += a0.x * a0.x + a0.y * a0.y + a0.z * a0.z + a0.w * a0.w
                + a1.x * a1.x + a1.y * a1.y + a1.z * a1.z + a1.w * a1.w;
        }
    }
    if (l == NLVL) {
#pragma unroll
        for (int o = 16; o > 0; o >>= 1) {
            ts += __shfl_xor_sync(0xffffffffu, ts, o);
            tq += __shfl_xor_sync(0xffffffffu, tq, o);
        }
        if (lane == 0) { red[warp] = ts; red[16 + warp] = tq; }
        CBAR();
        if (tid == 0) {
            float a = 0.f, b = 0.f;
#pragma unroll
            for (int j = 0; j < 16; j++) { a += red[j]; b += red[16 + j]; }
            g_psum[cta] += (double)a;
            g_psq[cta]  += (double)b;
        }
        CBAR();
    }
}

// ---------------- the persistent kernel --------------------------------------
__global__ void __launch_bounds__(NTHR_TOT, 1) persist_kernel(
    const float* __restrict__ x, const int* __restrict__ ei,
    const float* __restrict__ W, const float* __restrict__ att_src,
    const float* __restrict__ att_dst, const float* __restrict__ bias,
    const float* __restrict__ gamma, const float* __restrict__ beta,
    float* __restrict__ out,
    const float4* __restrict__ esrc, float4* __restrict__ edst, long long ec4)
{
    __shared__ float As[2][64][32];
    __shared__ float Bs[2][64][32];
    __shared__ float s_vsrc[D];
    __shared__ float s_vdst[D];
    __shared__ float red[32];
    __shared__ float sbc[2];

    const int cta = blockIdx.x;
    const int tid = threadIdx.x;

    // ===== pure-copy CTAs (20 SMs, all 20 warps copying) ======================
    if (cta >= NCOMP) {
        if (esrc != nullptr) {
            long long gw = (long long)NCOMP * CWARPS
                         + (long long)(cta - NCOMP) * WARPS_TOT + (tid >> 5);
            copy_work(esrc, edst, ec4, gw);
        }
        return;
    }

    // ===== copy warps inside compute CTAs =====================================
    if (tid >= NTHR) {
        if (esrc != nullptr) {
            long long gw = (long long)cta * CWARPS + ((tid - NTHR) >> 5);
            copy_work(esrc, edst, ec4, gw);
        }
        return;
    }

    // ===== compute warps =======================================================
    const int warp = tid >> 5, lane = tid & 31;
    int ls = 1 ^ *((volatile int*)&g_sense);

    // P0: v-vectors (per-CTA smem), rowdots, stats over x head
    if (tid < D) {
        float s = 0.f, t = 0.f;
        for (int k = 0; k < D; k++) {
            float w2 = W[k * D + tid];
            s = fmaf(w2, att_src[k], s);
            t = fmaf(w2, att_dst[k], t);
        }
        s_vsrc[tid] = s;
        s_vdst[tid] = t;
    }
    CBAR();

    for (int idx = cta * 16 + warp; idx < 2 * PER; idx += NCOMP * 16) {
        const float* A; const float* v; int r;
        if (idx < PER) { r = idx;       A = x;                    v = s_vsrc; }
        else           { r = idx - PER; A = x + (size_t)PER * D;  v = s_vdst; }
        const float4* a4 = (const float4*)(A + (size_t)r * D);
        const float4* v4 = (const float4*)v;
        float s = 0.f;
#pragma unroll
        for (int i = 0; i < 2; i++) {
            float4 a  = a4[i * 32 + lane];
            float4 vv = v4[i * 32 + lane];
            s += a.x * vv.x + a.y * vv.y + a.z * vv.z + a.w * vv.w;
        }
#pragma unroll
        for (int o = 16; o > 0; o >>= 1) s += __shfl_xor_sync(0xffffffffu, s, o);
        if (lane == 0) { if (idx < PER) g_asrc2[1][r] = s; else g_adst[r] = s; }
    }

    {
        float s = 0.f, q = 0.f;
        const float4* x4 = (const float4*)x;
        const int total4 = (NNODES - PER) * (D / 4);
        for (int i = cta * NTHR + tid; i < total4; i += NCOMP * NTHR) {
            float4 v = x4[i];
            s += v.x + v.y + v.z + v.w;
            q += v.x * v.x + v.y * v.y + v.z * v.z + v.w * v.w;
        }
#pragma unroll
        for (int o = 16; o > 0; o >>= 1) {
            s += __shfl_xor_sync(0xffffffffu, s, o);
            q += __shfl_xor_sync(0xffffffffu, q, o);
        }
        if (lane == 0) { red[warp] = s; red[16 + warp] = q; }
        CBAR();
        if (tid == 0) {
            float a = 0.f, b = 0.f;
#pragma unroll
            for (int j = 0; j < 16; j++) { a += red[j]; b += red[16 + j]; }
            g_psum[cta] = (double)a;     // overwrite: no zero-init needed
            g_psq[cta]  = (double)b;
        }
    }
    gbar(ls);

    // P1: H1 = x[layer0] @ W^T
    gemm_phase(x, W, g_H, As, Bs, cta, tid);
    gbar(ls);

    // chain
    for (int l = 1; l <= NLVL; l++) {
        agg_phase(ei, bias, x, l, s_vsrc, red, cta, tid);
        gbar(ls);
        if (l < NLVL) {
            gemm_phase(g_X2, W, g_H, As, Bs, cta, tid);
            gbar(ls);
        }
    }

    // norm
    if (warp == 0) {
        double ds = 0.0, dq = 0.0;
        for (int i = lane; i < NCOMP; i += 32) { ds += g_psum[i]; dq += g_psq[i]; }
#pragma unroll
        for (int o = 16; o > 0; o >>= 1) {
            ds += __shfl_xor_sync(0xffffffffu, ds, o);
            dq += __shfl_xor_sync(0xffffffffu, dq, o);
        }
        if (lane == 0) {
            double cnt  = (double)NNODES * D;
            double mean = ds / cnt;
            double var  = dq / cnt - mean * mean;
            sbc[0] = (float)mean;
            sbc[1] = rsqrtf((float)var + 1e-5f);
        }
    }
    CBAR();
    const float mu = sbc[0], rstd = sbc[1];
    const int total4 = NNODES * (D / 4);
    const int tail4  = (NNODES - PER) * (D / 4);
    for (int i = cta * NTHR + tid; i < total4; i += NCOMP * NTHR) {
        float4 v = (i < tail4) ? ((const float4*)x)[i] : ((const float4*)g_y)[i - tail4];
        int c4 = i & 63;
        float4 g = ((const float4*)gamma)[c4];
        float4 b = ((const float4*)beta)[c4];
        float4 o;
        o.x = (v.x - mu) * rstd * g.x + b.x;
        o.y = (v.y - mu) * rstd * g.y + b.y;
        o.z = (v.z - mu) * rstd * g.z + b.z;
        o.w = (v.w - mu) * rstd * g.w + b.w;
        ((float4*)out)[i] = o;
    }
}

// ---------------- launch ----------------
extern "C" void kernel_launch(void* const* d_in, const int* in_sizes, int n_in,
                              void* d_out, int out_size) {
    const float* x       = (const float*)d_in[0];
    const int*   ei      = (const int*)d_in[1];
    const float* eattr   = (const float*)d_in[2];
    const float* W       = (const float*)d_in[5];
    const float* att_src = (const float*)d_in[6];
    const float* att_dst = (const float*)d_in[7];
    const float* bias    = (const float*)d_in[8];
    const float* gamma   = (const float*)d_in[9];
    const float* beta    = (const float*)d_in[10];
    float* out = (float*)d_out;

    size_t eelems = (size_t)in_sizes[2];
    bool do_copy = ((size_t)out_size >= (size_t)NNODES * D + eelems);
    const float4* e4src = do_copy ? (const float4*)eattr : nullptr;
    float4* e4dst = do_copy ? (float4*)(out + (size_t)NNODES * D) : nullptr;
    long long ec4 = do_copy ? (long long)(eelems / 4) : 0;

    persist_kernel<<<NCTA, NTHR_TOT>>>(x, ei, W, att_src, att_dst, bias, gamma, beta,
                                       out, e4src, e4dst, ec4);
}

// round 15
// speedup vs baseline: 1.2426x; 1.1763x over previous
#include <cuda_runtime.h>
#include <cstdint>
#include <cstddef>

// Problem constants (fixed by setup_inputs: d=256, L=8, per=8192, deg=8)
#define D        256
#define PER      8192
#define NNODES   65536
#define DEG      8
#define EPL      65536
#define NLVL     7
#define NCTA     148                // total CTAs (one per SM)
#define NCOMP    128                // compute CTAs: 64 rows each = 8192
#define NTHR     512                // compute threads per compute CTA (16 warps)
#define CWARPS   4                  // copy warps inside each compute CTA
#define NTHR_TOT (NTHR + CWARPS * 32)   // 640
#define WARPS_TOT (NTHR_TOT / 32)   // 20 (pure-copy CTAs use all 20)
#define TOTAL_CW (NCOMP * CWARPS + (NCTA - NCOMP) * WARPS_TOT)   // 912 copy warps

// dynamic smem: As 64x256 f32 (64KB) + Bs 2x256x32 f32 (64KB)
#define AS_BYTES (64 * 256 * 4)
#define BS_BYTES (2 * 256 * 32 * 4)
#define DYN_SMEM (AS_BYTES + BS_BYTES)

// named barrier for the 512 compute threads only (copy warps never join)
#define CBAR() asm volatile("bar.sync 1, %0;" :: "n"(NTHR) : "memory")

// ---------------- device scratch (no allocation allowed) ----------------
__device__ float  g_Ha[PER * D];         // H ping
__device__ float  g_Hb[PER * D];         // H pong
__device__ float  g_y[PER * D];          // y = x + x2 for last-layer rows
__device__ float  g_asrc2[2][PER];       // ping-pong a_src
__device__ float  g_adst[PER];
__device__ double g_psum[NCOMP];         // per-CTA LN partials (no atomics)
__device__ double g_psq[NCOMP];
__device__ int    g_count = 0;           // grid barrier state
__device__ int    g_sense = 0;

__device__ __forceinline__ void cp16(uint32_t dst, const float* src) {
    asm volatile("cp.async.cg.shared.global [%0], [%1], 16;\n" :: "r"(dst), "l"(src));
}

__device__ __forceinline__ void mma_tf32(float* c, const uint32_t* a, const uint32_t* b) {
    asm volatile(
        "mma.sync.aligned.m16n8k8.row.col.f32.tf32.tf32.f32 "
        "{%0,%1,%2,%3}, {%4,%5,%6,%7}, {%8,%9}, {%0,%1,%2,%3};\n"
        : "+f"(c[0]), "+f"(c[1]), "+f"(c[2]), "+f"(c[3])
        : "r"(a[0]), "r"(a[1]), "r"(a[2]), "r"(a[3]), "r"(b[0]), "r"(b[1]));
}

// grid-wide barrier over compute warps of the NCOMP compute CTAs
__device__ __forceinline__ void gbar(int& ls) {
    CBAR();
    if (threadIdx.x == 0) {
        __threadfence();
        if (atomicAdd(&g_count, 1) == NCOMP - 1) {
            g_count = 0;
            __threadfence();
            atomicExch(&g_sense, ls);
        } else {
            while (*(volatile int*)&g_sense != ls) __nanosleep(64);
            __threadfence();
        }
    }
    CBAR();
    ls ^= 1;
}

// ---------------- copy worker: batch-8 register pipeline (R8 winner) ---------
__device__ __forceinline__ void copy_work(const float4* __restrict__ esrc,
                                          float4* __restrict__ edst,
                                          long long ec4, long long gw)
{
    const int lane = threadIdx.x & 31;
    const long long stride = (long long)TOTAL_CW * 32;
    long long i = gw * 32 + lane;
    float4 v[8];
    for (; i + 7 * stride < ec4; i += 8 * stride) {
#pragma unroll
        for (int u = 0; u < 8; u++) v[u] = __ldcs(&esrc[i + u * stride]);
#pragma unroll
        for (int u = 0; u < 8; u++) __stcs(&edst[i + u * stride], v[u]);
    }
    for (; i < ec4; i += stride) __stcs(&edst[i], __ldcs(&esrc[i]));
}

// ---------------- GEMM from smem As: Hout[64 x 256] = As @ W^T ----------------
// 16 warps, warp tile 16x64 (4m x 4n), K=256 in 8 chunks of 32 (Bs double-buf).
__device__ __forceinline__ void gemm_from_smem(float* As, float* Bs,
                                               const float* __restrict__ W,
                                               float* __restrict__ Hout,
                                               int cta, int tid)
{
    const int warp = tid >> 5, lane = tid & 31;
    const int wm = (warp & 3) * 16;          // m offset within 64
    const int wn = (warp >> 2) * 64;         // n offset within 256
    const uint32_t as_base = (uint32_t)__cvta_generic_to_shared(As);
    const uint32_t bs_base = (uint32_t)__cvta_generic_to_shared(Bs);

    float acc[8][4];
#pragma unroll
    for (int i = 0; i < 8; i++)
#pragma unroll
        for (int j = 0; j < 4; j++) acc[i][j] = 0.f;

    // Bs staging: chunk = W[0..256][c*32 .. c*32+32) -> 256 rows x 8 segs, swizzled
    auto stageB = [&](int buf, int c) {
#pragma unroll
        for (int i = 0; i < 4; i++) {
            int f = tid + i * NTHR;
            int r = f >> 3, sg = f & 7;
            const float* src = W + (size_t)r * D + c * 32 + sg * 4;
            uint32_t dst = bs_base + (uint32_t)(((buf * 256 + r) * 8 + (sg ^ (r & 7))) * 16);
            cp16(dst, src);
        }
        asm volatile("cp.async.commit_group;\n" ::: "memory");
    };

    stageB(0, 0);
#pragma unroll 1
    for (int c = 0; c < 8; c++) {
        if (c + 1 < 8) {
            stageB((c + 1) & 1, c + 1);
            asm volatile("cp.async.wait_group 1;\n" ::: "memory");
        } else {
            asm volatile("cp.async.wait_group 0;\n" ::: "memory");
        }
        CBAR();
        const int buf = c & 1;
#pragma unroll
        for (int kk = 0; kk < 4; kk++) {
            uint32_t a[4], b[8][2];
            {   // A frag: rows wm..wm+15 of As, k8 = c*8+kk*2(+hi)
                int arow = wm + (lane & 7) + ((lane & 8) ? 8 : 0);
                int seg  = c * 8 + kk * 2 + ((lane >> 4) & 1);
                int sw   = (seg & ~7) | ((seg ^ arow) & 7);
                uint32_t aaddr = as_base + (uint32_t)((arow * 64 + sw) * 16);
                asm volatile("ldmatrix.sync.aligned.m8n8.x4.shared.b16 {%0,%1,%2,%3}, [%4];\n"
                             : "=r"(a[0]), "=r"(a[1]), "=r"(a[2]), "=r"(a[3]) : "r"(aaddr));
            }
#pragma unroll
            for (int jp = 0; jp < 4; jp++) {   // B frags: n = wn+jp*16 .. +16
                int brow = wn + jp * 16 + (lane & 7) + ((lane & 16) ? 8 : 0);
                int bsg  = (kk * 2 + ((lane >> 3) & 1)) ^ (brow & 7);
                uint32_t baddr = bs_base + (uint32_t)(((buf * 256 + brow) * 8 + bsg) * 16);
                asm volatile("ldmatrix.sync.aligned.m8n8.x4.shared.b16 {%0,%1,%2,%3}, [%4];\n"
                             : "=r"(b[jp * 2][0]), "=r"(b[jp * 2][1]),
                               "=r"(b[jp * 2 + 1][0]), "=r"(b[jp * 2 + 1][1])
                             : "r"(baddr));
            }
#pragma unroll
            for (int nt = 0; nt < 8; nt++) mma_tf32(acc[nt], a, b[nt]);
        }
        CBAR();
    }
    // epilogue: write to Hout (global, ping-pong buffer)
    int row0 = cta * 64 + wm + (lane >> 2);
#pragma unroll
    for (int nt = 0; nt < 8; nt++) {
        int col = wn + nt * 8 + (lane & 3) * 2;
        *reinterpret_cast<float2*>(&Hout[(size_t)row0 * D + col]) =
            make_float2(acc[nt][0], acc[nt][1]);
        *reinterpret_cast<float2*>(&Hout[(size_t)(row0 + 8) * D + col]) =
            make_float2(acc[nt][2], acc[nt][3]);
    }
}

// ---------------- aggregate level l into smem As (or y for last level) -------
__device__ __forceinline__ void agg_to_smem(const int* __restrict__ ei,
                                            const float* __restrict__ bias,
                                            const float* __restrict__ x,
                                            const float* __restrict__ Hin,
                                            float* As, int l, const float* s_vsrc,
                                            float* red, int cta, int tid)
{
    const int warp = tid >> 5, lane = tid & 31;
    const float* asrc = g_asrc2[l & 1];
    float* anext = g_asrc2[(l + 1) & 1];
    const float4* H4 = (const float4*)Hin;
    const float4* b4 = (const float4*)bias;
    float ts = 0.f, tq = 0.f;
    const int lastlvl = (l == NLVL);

#pragma unroll 1
    for (int k = 0; k < 4; k++) {
        const int lr  = warp + k * 16;          // local row 0..63
        const int row = cta * 64 + lr;          // global dst row in level
        const int eb = (l - 1) * EPL + row * DEG;
        int sj[DEG]; float p[DEG];
        float ad = (l == 1) ? g_adst[row] : 0.f;
        float m = -1e30f;
#pragma unroll
        for (int j = 0; j < DEG; j++) {
            int s = ei[eb + j] - (l - 1) * PER;
            sj[j] = s;
            float a = asrc[s] + ad;
            a = a > 0.f ? a : 0.2f * a;           // leaky_relu 0.2
            p[j] = a;
            m = fmaxf(m, a);
        }
        float den = 0.f;
#pragma unroll
        for (int j = 0; j < DEG; j++) { p[j] = __expf(p[j] - m); den += p[j]; }
        float inv = 1.f / den;
#pragma unroll
        for (int j = 0; j < DEG; j++) p[j] *= inv;

        float4 a0 = b4[lane], a1 = b4[32 + lane];
#pragma unroll
        for (int j = 0; j < DEG; j++) {
            float4 h0 = H4[(size_t)sj[j] * 64 + lane];
            float4 h1 = H4[(size_t)sj[j] * 64 + 32 + lane];
            a0.x = fmaf(p[j], h0.x, a0.x); a0.y = fmaf(p[j], h0.y, a0.y);
            a0.z = fmaf(p[j], h0.z, a0.z); a0.w = fmaf(p[j], h0.w, a0.w);
            a1.x = fmaf(p[j], h1.x, a1.x); a1.y = fmaf(p[j], h1.y, a1.y);
            a1.z = fmaf(p[j], h1.z, a1.z); a1.w = fmaf(p[j], h1.w, a1.w);
        }
        if (!lastlvl) {
            // store to smem As with xor-by-row swizzle (16B seg granularity)
            int sw0 = (lane & ~7) | ((lane ^ lr) & 7);
            int sw1 = 32 + sw0 - (lane & 7) + (((32 + lane) ^ lr) & 7);
            // note: (32+lane)&7 == lane&7, so sw1 = 32 + ((lane&~7)|((lane^lr)&7))
            sw1 = 32 + sw0;
            ((float4*)As)[lr * 64 + sw0] = a0;
            ((float4*)As)[lr * 64 + sw1] = a1;
            const float4* v4 = (const float4*)s_vsrc;
            float4 v0 = v4[lane], v1 = v4[32 + lane];
            float d = a0.x * v0.x + a0.y * v0.y + a0.z * v0.z + a0.w * v0.w
                    + a1.x * v1.x + a1.y * v1.y + a1.z * v1.z + a1.w * v1.w;
#pragma unroll
            for (int o = 16; o > 0; o >>= 1) d += __shfl_xor_sync(0xffffffffu, d, o);
            if (lane == 0) anext[row] = d;
        } else {
            float4 x0 = ((const float4*)x)[(size_t)(7 * PER + row) * 64 + lane];
            float4 x1 = ((const float4*)x)[(size_t)(7 * PER + row) * 64 + 32 + lane];
            a0.x += x0.x; a0.y += x0.y; a0.z += x0.z; a0.w += x0.w;
            a1.x += x1.x; a1.y += x1.y; a1.z += x1.z; a1.w += x1.w;
            ((float4*)g_y)[(size_t)row * 64 + lane]      = a0;
            ((float4*)g_y)[(size_t)row * 64 + 32 + lane] = a1;
            ts += a0.x + a0.y + a0.z + a0.w + a1.x + a1.y + a1.z + a1.w;
            tq += a0.x * a0.x + a0.y * a0.y + a0.z * a0.z + a0.w * a0.w
                + a1.x * a1.x + a1.y * a1.y + a1.z * a1.z + a1.w * a1.w;
        }
    }
    if (lastlvl) {
#pragma unroll
        for (int o = 16; o > 0; o >>= 1) {
            ts += __shfl_xor_sync(0xffffffffu, ts, o);
            tq += __shfl_xor_sync(0xffffffffu, tq, o);
        }
        if (lane == 0) { red[warp] = ts; red[16 + warp] = tq; }
        CBAR();
        if (tid == 0) {
            float a = 0.f, b = 0.f;
#pragma unroll
            for (int j = 0; j < 16; j++) { a += red[j]; b += red[16 + j]; }
            g_psum[cta] += (double)a;
            g_psq[cta]  += (double)b;
        }
    }
}

// ---------------- the persistent kernel --------------------------------------
__global__ void __launch_bounds__(NTHR_TOT, 1) persist_kernel(
    const float* __restrict__ x, const int* __restrict__ ei,
    const float* __restrict__ W, const float* __restrict__ att_src,
    const float* __restrict__ att_dst, const float* __restrict__ bias,
    const float* __restrict__ gamma, const float* __restrict__ beta,
    float* __restrict__ out,
    const float4* __restrict__ esrc, float4* __restrict__ edst, long long ec4)
{
    __shared__ float s_vsrc[D];
    __shared__ float s_vdst[D];
    __shared__ float red[32];
    __shared__ float sbc[2];
    extern __shared__ float dyn[];
    float* As = dyn;                          // 64 x 256 (swizzled 16B segs)
    float* Bs = dyn + AS_BYTES / 4;           // 2 x 256 x 32 (swizzled)

    const int cta = blockIdx.x;
    const int tid = threadIdx.x;

    // ===== pure-copy CTAs (20 SMs, all 20 warps copying) ======================
    if (cta >= NCOMP) {
        if (esrc != nullptr) {
            long long gw = (long long)NCOMP * CWARPS
                         + (long long)(cta - NCOMP) * WARPS_TOT + (tid >> 5);
            copy_work(esrc, edst, ec4, gw);
        }
        return;
    }

    // ===== copy warps inside compute CTAs =====================================
    if (tid >= NTHR) {
        if (esrc != nullptr) {
            long long gw = (long long)cta * CWARPS + ((tid - NTHR) >> 5);
            copy_work(esrc, edst, ec4, gw);
        }
        return;
    }

    // ===== compute warps =======================================================
    const int warp = tid >> 5, lane = tid & 31;
    int ls = 1 ^ *((volatile int*)&g_sense);

    // P0: v-vectors (per-CTA smem), rowdots, stats over x head
    if (tid < D) {
        float s = 0.f, t = 0.f;
        for (int k = 0; k < D; k++) {
            float w2 = W[k * D + tid];
            s = fmaf(w2, att_src[k], s);
            t = fmaf(w2, att_dst[k], t);
        }
        s_vsrc[tid] = s;
        s_vdst[tid] = t;
    }
    CBAR();

    for (int idx = cta * 16 + warp; idx < 2 * PER; idx += NCOMP * 16) {
        const float* A; const float* v; int r;
        if (idx < PER) { r = idx;       A = x;                    v = s_vsrc; }
        else           { r = idx - PER; A = x + (size_t)PER * D;  v = s_vdst; }
        const float4* a4 = (const float4*)(A + (size_t)r * D);
        const float4* v4 = (const float4*)v;
        float s = 0.f;
#pragma unroll
        for (int i = 0; i < 2; i++) {
            float4 a  = a4[i * 32 + lane];
            float4 vv = v4[i * 32 + lane];
            s += a.x * vv.x + a.y * vv.y + a.z * vv.z + a.w * vv.w;
        }
#pragma unroll
        for (int o = 16; o > 0; o >>= 1) s += __shfl_xor_sync(0xffffffffu, s, o);
        if (lane == 0) { if (idx < PER) g_asrc2[1][r] = s; else g_adst[r] = s; }
    }

    {
        float s = 0.f, q = 0.f;
        const float4* x4 = (const float4*)x;
        const int total4 = (NNODES - PER) * (D / 4);
        for (int i = cta * NTHR + tid; i < total4; i += NCOMP * NTHR) {
            float4 v = x4[i];
            s += v.x + v.y + v.z + v.w;
            q += v.x * v.x + v.y * v.y + v.z * v.z + v.w * v.w;
        }
#pragma unroll
        for (int o = 16; o > 0; o >>= 1) {
            s += __shfl_xor_sync(0xffffffffu, s, o);
            q += __shfl_xor_sync(0xffffffffu, q, o);
        }
        if (lane == 0) { red[warp] = s; red[16 + warp] = q; }
        CBAR();
        if (tid == 0) {
            float a = 0.f, b = 0.f;
#pragma unroll
            for (int j = 0; j < 16; j++) { a += red[j]; b += red[16 + j]; }
            g_psum[cta] = (double)a;     // overwrite: no zero-init needed
            g_psq[cta]  = (double)b;
        }
    }
    // no gbar needed yet: next phase (load x -> As, gemm) is CTA-local until
    // the H write, and nothing reads H before the gbar after gemm.

    // ===== level-1 GEMM: As <- x[layer0] rows (this CTA's 64), gemm -> Ha =====
    {
#pragma unroll
        for (int k = 0; k < 4; k++) {
            int lr = warp + k * 16;
            const float4* xr = (const float4*)(x + (size_t)(cta * 64 + lr) * D);
            float4 a0 = xr[lane], a1 = xr[32 + lane];
            int sw0 = (lane & ~7) | ((lane ^ lr) & 7);
            ((float4*)As)[lr * 64 + sw0]      = a0;
            ((float4*)As)[lr * 64 + 32 + sw0] = a1;
        }
        CBAR();
        gemm_from_smem(As, Bs, W, g_Ha, cta, tid);
    }
    gbar(ls);   // H^1 complete everywhere (also covers P0 scalars)

    // ===== chain: one gbar per level ==========================================
    // level l: agg from H^l (buf (l+1)&1: Ha=buf0 holds H^1) -> As ; gemm -> H^{l+1}
    float* Hbuf[2];
    {   // resolve device-symbol addresses once
        Hbuf[0] = g_Ha; Hbuf[1] = g_Hb;
    }
#pragma unroll 1
    for (int l = 1; l < NLVL; l++) {
        const float* Hin = Hbuf[(l + 1) & 1];
        float* Hout = Hbuf[l & 1];
        agg_to_smem(ei, bias, x, Hin, As, l, s_vsrc, red, cta, tid);
        CBAR();                                  // As ready (CTA-local)
        gemm_from_smem(As, Bs, W, Hout, cta, tid);
        gbar(ls);                                // H^{l+1} complete everywhere
    }
    // level 7: aggregate to y + stats
    agg_to_smem(ei, bias, x, Hbuf[0], As, NLVL, s_vsrc, red, cta, tid);
    gbar(ls);   // stats complete everywhere

    // ===== norm ================================================================
    if (warp == 0) {
        double ds = 0.0, dq = 0.0;
        for (int i = lane; i < NCOMP; i += 32) { ds += g_psum[i]; dq += g_psq[i]; }
#pragma unroll
        for (int o = 16; o > 0; o >>= 1) {
            ds += __shfl_xor_sync(0xffffffffu, ds, o);
            dq += __shfl_xor_sync(0xffffffffu, dq, o);
        }
        if (lane == 0) {
            double cnt  = (double)NNODES * D;
            double mean = ds / cnt;
            double var  = dq / cnt - mean * mean;
            sbc[0] = (float)mean;
            sbc[1] = rsqrtf((float)var + 1e-5f);
        }
    }
    CBAR();
    const float mu = sbc[0], rstd = sbc[1];
    const int total4 = NNODES * (D / 4);
    const int tail4  = (NNODES - PER) * (D / 4);
    for (int i = cta * NTHR + tid; i < total4; i += NCOMP * NTHR) {
        float4 v = (i < tail4) ? ((const float4*)x)[i] : ((const float4*)g_y)[i - tail4];
        int c4 = i & 63;
        float4 g = ((const float4*)gamma)[c4];
        float4 b = ((const float4*)beta)[c4];
        float4 o;
        o.x = (v.x - mu) * rstd * g.x + b.x;
        o.y = (v.y - mu) * rstd * g.y + b.y;
        o.z = (v.z - mu) * rstd * g.z + b.z;
        o.w = (v.w - mu) * rstd * g.w + b.w;
        ((float4*)out)[i] = o;
    }
}

// ---------------- launch ----------------
extern "C" void kernel_launch(void* const* d_in, const int* in_sizes, int n_in,
                              void* d_out, int out_size) {
    const float* x       = (const float*)d_in[0];
    const int*   ei      = (const int*)d_in[1];
    const float* eattr   = (const float*)d_in[2];
    const float* W       = (const float*)d_in[5];
    const float* att_src = (const float*)d_in[6];
    const float* att_dst = (const float*)d_in[7];
    const float* bias    = (const float*)d_in[8];
    const float* gamma   = (const float*)d_in[9];
    const float* beta    = (const float*)d_in[10];
    float* out = (float*)d_out;

    static bool attr_set = false;
    if (!attr_set) {
        cudaFuncSetAttribute(persist_kernel,
                             cudaFuncAttributeMaxDynamicSharedMemorySize, DYN_SMEM);
        attr_set = true;
    }

    size_t eelems = (size_t)in_sizes[2];
    bool do_copy = ((size_t)out_size >= (size_t)NNODES * D + eelems);
    const float4* e4src = do_copy ? (const float4*)eattr : nullptr;
    float4* e4dst = do_copy ? (float4*)(out + (size_t)NNODES * D) : nullptr;
    long long ec4 = do_copy ? (long long)(eelems / 4) : 0;

    persist_kernel<<<NCTA, NTHR_TOT, DYN_SMEM>>>(x, ei, W, att_src, att_dst, bias,
                                                 gamma, beta, out, e4src, e4dst, ec4);
}